// round 1
// baseline (speedup 1.0000x reference)
#include <cuda_runtime.h>
#include <cuda_bf16.h>

// Gps: 2-layer graph encoder.
//   agg0 = 0.5 * adj1 @ f1                          [16384,256]
//   h    = lrelu([gather(feat,seed) | agg0] @ W1^T) [16384,256]
//   aggm = 0.125 * (sum of 4-row groups of adj2) @ f2   (== 0.5*mean trick)
//   emb  = lrelu([h | aggm] @ W2^T)                 [16384,256]  -> d_out
//
// All GEMMs: SIMT fp32, 128x128x16 tiles, 8x8 micro-tile using packed
// fma.rn.f32x2 (2 FMA/lane/instr) for 2x FFMA throughput.

#define BM 128
#define BN 128
#define BK 16
#define APAD 4
#define BPAD 4

#define N_SEED 16384
#define NOUT 256

__device__ float g_agg0[N_SEED * 256];
__device__ float g_aggm[N_SEED * 256];
__device__ float g_h[N_SEED * 256];

__device__ __forceinline__ unsigned long long splat2(float a) {
    unsigned long long r;
    asm("mov.b64 %0, {%1, %1};" : "=l"(r) : "f"(a));
    return r;
}
__device__ __forceinline__ void fma2(unsigned long long& acc,
                                     unsigned long long a,
                                     unsigned long long b) {
    asm("fma.rn.f32x2 %0, %1, %2, %0;" : "+l"(acc) : "l"(a), "l"(b));
}
__device__ __forceinline__ float2 unpack2(unsigned long long v) {
    float2 r;
    asm("mov.b64 {%0, %1}, %2;" : "=f"(r.x), "=f"(r.y) : "l"(v));
    return r;
}

// ---------------------------------------------------------------------------
// Big GEMM: C[M,256] = scale * A' @ B
//   AVG4=false: A' = A  (A is [M,K] row-major)
//   AVG4=true : A'[m,:] = sum of rows 4m..4m+3 of A  (A is [4M,K])
// B is [K,256] row-major. M = 16384 (grid fixed), no bounds checks needed.
// ---------------------------------------------------------------------------
template <bool AVG4>
__global__ void __launch_bounds__(256, 2)
gemm_big(const float* __restrict__ A, const float* __restrict__ B,
         float* __restrict__ C, int K, float scale) {
    __shared__ __align__(16) float As[BK][BM + APAD];
    __shared__ __align__(16) float Bs[BK][BN + BPAD];

    const int tid = threadIdx.x;
    const int bm = blockIdx.x, bn = blockIdx.y;
    const int tx = tid & 15, ty = tid >> 4;

    const int a_row = tid >> 2;         // 0..63
    const int a_col = (tid & 3) << 2;   // 0,4,8,12
    const int b_row = tid >> 5;         // 0..7
    const int b_col = (tid & 31) << 2;  // 0..124

    unsigned long long acc[8][4];
#pragma unroll
    for (int i = 0; i < 8; i++)
#pragma unroll
        for (int j = 0; j < 4; j++) acc[i][j] = 0ull;

    for (int k0 = 0; k0 < K; k0 += BK) {
        // --- load A tile (transposed into SMEM) ---
#pragma unroll
        for (int r = 0; r < 2; r++) {
            const int m = bm * BM + a_row + r * 64;
            float4 v;
            if (AVG4) {
                const float* p = A + (size_t)m * 4 * K + k0 + a_col;
                float4 v0 = *(const float4*)p;
                float4 v1 = *(const float4*)(p + K);
                float4 v2 = *(const float4*)(p + 2 * (size_t)K);
                float4 v3 = *(const float4*)(p + 3 * (size_t)K);
                v.x = (v0.x + v1.x) + (v2.x + v3.x);
                v.y = (v0.y + v1.y) + (v2.y + v3.y);
                v.z = (v0.z + v1.z) + (v2.z + v3.z);
                v.w = (v0.w + v1.w) + (v2.w + v3.w);
            } else {
                v = *(const float4*)(A + (size_t)m * K + k0 + a_col);
            }
            As[a_col + 0][a_row + r * 64] = v.x;
            As[a_col + 1][a_row + r * 64] = v.y;
            As[a_col + 2][a_row + r * 64] = v.z;
            As[a_col + 3][a_row + r * 64] = v.w;
        }
        // --- load B tile ---
#pragma unroll
        for (int r = 0; r < 2; r++) {
            const int k = b_row + r * 8;
            *(float4*)&Bs[k][b_col] =
                *(const float4*)(B + (size_t)(k0 + k) * NOUT + bn * BN + b_col);
        }
        __syncthreads();

#pragma unroll
        for (int kk = 0; kk < BK; kk++) {
            float a[8];
            *(float4*)&a[0] = *(const float4*)&As[kk][ty * 4];
            *(float4*)&a[4] = *(const float4*)&As[kk][64 + ty * 4];
            unsigned long long b[4];
            {
                ulonglong2 t0 = *(const ulonglong2*)&Bs[kk][tx * 4];
                ulonglong2 t1 = *(const ulonglong2*)&Bs[kk][64 + tx * 4];
                b[0] = t0.x; b[1] = t0.y; b[2] = t1.x; b[3] = t1.y;
            }
#pragma unroll
            for (int i = 0; i < 8; i++) {
                unsigned long long a2 = splat2(a[i]);
#pragma unroll
                for (int j = 0; j < 4; j++) fma2(acc[i][j], a2, b[j]);
            }
        }
        __syncthreads();
    }

#pragma unroll
    for (int i = 0; i < 8; i++) {
        const int m = bm * BM + ((i < 4) ? (ty * 4 + i) : (64 + ty * 4 + i - 4));
#pragma unroll
        for (int j = 0; j < 4; j++) {
            const int n =
                bn * BN + ((j < 2) ? (tx * 4 + j * 2) : (64 + tx * 4 + (j - 2) * 2));
            float2 v = unpack2(acc[i][j]);
            v.x *= scale;
            v.y *= scale;
            *(float2*)(C + (size_t)m * NOUT + n) = v;
        }
    }
}

// ---------------------------------------------------------------------------
// Concat GEMM: C[M,256] = leakyrelu( [A1 | A2] @ W^T ), K = 512.
//   A1: [*,256]; if GATHER, row m comes from A1[seed[m]]. A2: [M,256].
//   W: [256,512] row-major; B[k][n] = W[n][k].
// ---------------------------------------------------------------------------
template <bool GATHER>
__global__ void __launch_bounds__(256, 2)
gemm_cat(const float* __restrict__ A1, const float* __restrict__ A2,
         const float* __restrict__ W, const int* __restrict__ seed,
         float* __restrict__ C) {
    __shared__ __align__(16) float As[BK][BM + APAD];
    __shared__ __align__(16) float Bs[BK][BN + BPAD];

    const int tid = threadIdx.x;
    const int bm = blockIdx.x, bn = blockIdx.y;
    const int tx = tid & 15, ty = tid >> 4;

    const int a_row = tid >> 2;
    const int a_col = (tid & 3) << 2;
    const int w_n = tid >> 2;          // 0..63
    const int w_k = (tid & 3) << 2;    // 0,4,8,12

    // hoist gather indices
    int src_row[2];
#pragma unroll
    for (int r = 0; r < 2; r++) {
        const int m = bm * BM + a_row + r * 64;
        src_row[r] = GATHER ? seed[m] : m;
    }

    unsigned long long acc[8][4];
#pragma unroll
    for (int i = 0; i < 8; i++)
#pragma unroll
        for (int j = 0; j < 4; j++) acc[i][j] = 0ull;

    for (int k0 = 0; k0 < 512; k0 += BK) {
#pragma unroll
        for (int r = 0; r < 2; r++) {
            const int m = bm * BM + a_row + r * 64;
            float4 v;
            if (k0 < 256) {
                v = *(const float4*)(A1 + (size_t)src_row[r] * 256 + k0 + a_col);
            } else {
                v = *(const float4*)(A2 + (size_t)m * 256 + (k0 - 256) + a_col);
            }
            As[a_col + 0][a_row + r * 64] = v.x;
            As[a_col + 1][a_row + r * 64] = v.y;
            As[a_col + 2][a_row + r * 64] = v.z;
            As[a_col + 3][a_row + r * 64] = v.w;
        }
        // B tile (transposed load from W)
#pragma unroll
        for (int r = 0; r < 2; r++) {
            const int n = w_n + r * 64;
            float4 w =
                *(const float4*)(W + (size_t)(bn * BN + n) * 512 + k0 + w_k);
            Bs[w_k + 0][n] = w.x;
            Bs[w_k + 1][n] = w.y;
            Bs[w_k + 2][n] = w.z;
            Bs[w_k + 3][n] = w.w;
        }
        __syncthreads();

#pragma unroll
        for (int kk = 0; kk < BK; kk++) {
            float a[8];
            *(float4*)&a[0] = *(const float4*)&As[kk][ty * 4];
            *(float4*)&a[4] = *(const float4*)&As[kk][64 + ty * 4];
            unsigned long long b[4];
            {
                ulonglong2 t0 = *(const ulonglong2*)&Bs[kk][tx * 4];
                ulonglong2 t1 = *(const ulonglong2*)&Bs[kk][64 + tx * 4];
                b[0] = t0.x; b[1] = t0.y; b[2] = t1.x; b[3] = t1.y;
            }
#pragma unroll
            for (int i = 0; i < 8; i++) {
                unsigned long long a2 = splat2(a[i]);
#pragma unroll
                for (int j = 0; j < 4; j++) fma2(acc[i][j], a2, b[j]);
            }
        }
        __syncthreads();
    }

#pragma unroll
    for (int i = 0; i < 8; i++) {
        const int m = bm * BM + ((i < 4) ? (ty * 4 + i) : (64 + ty * 4 + i - 4));
#pragma unroll
        for (int j = 0; j < 4; j++) {
            const int n =
                bn * BN + ((j < 2) ? (tx * 4 + j * 2) : (64 + tx * 4 + (j - 2) * 2));
            float2 v = unpack2(acc[i][j]);
            v.x = (v.x >= 0.0f) ? v.x : 0.01f * v.x;
            v.y = (v.y >= 0.0f) ? v.y : 0.01f * v.y;
            *(float2*)(C + (size_t)m * NOUT + n) = v;
        }
    }
}

extern "C" void kernel_launch(void* const* d_in, const int* in_sizes, int n_in,
                              void* d_out, int out_size) {
    const float* feature_matrix = (const float*)d_in[0];  // [100000,256]
    const float* adj1 = (const float*)d_in[1];            // [16384,4096]
    const float* f1 = (const float*)d_in[2];              // [4096,256]
    const float* adj2 = (const float*)d_in[3];            // [65536,2048]
    const float* f2 = (const float*)d_in[4];              // [2048,256]
    const float* W1 = (const float*)d_in[5];              // [256,512]
    const float* W2 = (const float*)d_in[6];              // [256,512]
    const int* seed = (const int*)d_in[7];                // [16384] int32
    float* out = (float*)d_out;                           // [16384,256]

    float *agg0, *aggm, *h;
    cudaGetSymbolAddress((void**)&agg0, g_agg0);
    cudaGetSymbolAddress((void**)&aggm, g_aggm);
    cudaGetSymbolAddress((void**)&h, g_h);

    dim3 grid(N_SEED / BM, NOUT / BN);  // (128, 2)
    dim3 blk(256);

    // agg0 = 0.5 * adj1 @ f1
    gemm_big<false><<<grid, blk>>>(adj1, f1, agg0, 4096, 0.5f);
    // aggm = 0.125 * (4-row-sum of adj2) @ f2   (= 0.5 * mean, folded)
    gemm_big<true><<<grid, blk>>>(adj2, f2, aggm, 2048, 0.125f);
    // h = lrelu([gather(feat,seed) | agg0] @ W1^T)
    gemm_cat<true><<<grid, blk>>>(feature_matrix, agg0, W1, seed, h);
    // emb = lrelu([h | aggm] @ W2^T)
    gemm_cat<false><<<grid, blk>>>(h, aggm, W2, nullptr, out);
}